// round 6
// baseline (speedup 1.0000x reference)
#include <cuda_runtime.h>

#define TT 512
#define BB 32
#define HH 512
#define NREC 128          // barrier-participating blocks (2 dirs x 64)
#define NEMB 12           // embedding-copy blocks (no barrier)

__device__ float g_h[2][2][BB * HH];      // [dir][parity][b*H+j]
__device__ unsigned int g_flags[NREC];    // monotonic barrier flags (persist across replays)
__device__ unsigned int g_dead;           // poison: set if a barrier ever times out

typedef unsigned long long ull;

static __device__ __forceinline__ ull pk(float x, float y) {
    ull r; asm("mov.b64 %0,{%1,%2};" : "=l"(r) : "f"(x), "f"(y)); return r;
}
static __device__ __forceinline__ void up(ull v, float& x, float& y) {
    asm("mov.b64 {%0,%1},%2;" : "=f"(x), "=f"(y) : "l"(v));
}
static __device__ __forceinline__ ull fma2(ull a, ull b, ull c) {
    ull d; asm("fma.rn.f32x2 %0,%1,%2,%3;" : "=l"(d) : "l"(a), "l"(b), "l"(c)); return d;
}
static __device__ __forceinline__ ull add2(ull a, ull b) {
    ull d; asm("add.rn.f32x2 %0,%1,%2;" : "=l"(d) : "l"(a), "l"(b)); return d;
}
static __device__ __forceinline__ float sigm(float x) {
    return __fdividef(1.f, 1.f + __expf(-x));
}
static __device__ __forceinline__ float tanh_(float x) {
    float a = fabsf(x), e = __expf(-2.f * a);
    return copysignf(__fdividef(1.f - e, 1.f + e), x);
}

// 8 packed FMAs: v broadcast over 4 k, into (i,f) and (g,o) accumulator pairs
static __device__ __forceinline__ void mac4(const ull* W01, const ull* W23, int q4, float4 v,
                                            ull& a0, ull& a1, ull& a2, ull& a3) {
    ull d0 = pk(v.x, v.x), d1 = pk(v.y, v.y), d2 = pk(v.z, v.z), d3 = pk(v.w, v.w);
    a0 = fma2(W01[q4 + 0], d0, a0); a2 = fma2(W23[q4 + 0], d0, a2);
    a1 = fma2(W01[q4 + 1], d1, a1); a3 = fma2(W23[q4 + 1], d1, a3);
    a0 = fma2(W01[q4 + 2], d2, a0); a2 = fma2(W23[q4 + 2], d2, a2);
    a1 = fma2(W01[q4 + 3], d3, a1); a3 = fma2(W23[q4 + 3], d3, a3);
}

// split barrier: arrive (non-blocking) / wait (poll, timeout-poisoned)
static __device__ __forceinline__ void barrier_arrive(int bid, unsigned int tgt) {
    __threadfence();                       // each thread's prior stores visible
    __syncthreads();                       // ...before tid0 publishes the flag
    if (threadIdx.x == 0) atomicExch(&g_flags[bid], tgt);
}
static __device__ __forceinline__ void barrier_wait(int dir, unsigned int tgt) {
    if (threadIdx.x < 32) {
        volatile unsigned int* f = g_flags + dir * 64;
        volatile unsigned int* dead = &g_dead;
        unsigned int it = 0;
        bool ok;
        do {
            unsigned int a = f[threadIdx.x], b = f[threadIdx.x + 32];
            ok = ((int)(a - tgt) >= 0) && ((int)(b - tgt) >= 0);
            if (++it > (1u << 18)) {       // never reached in a healthy run
                if (threadIdx.x == 0) atomicExch(&g_dead, 1u);
                break;
            }
        } while (!__all_sync(0xffffffffu, ok) && *dead == 0u);
        __threadfence();
    }
    __syncthreads();
}

extern __shared__ float h_sm[];               // BB*HH floats = 64KB

__global__ void __launch_bounds__(256, 1) bilstm_kernel(
    const int* __restrict__ seq, const int* __restrict__ lens,
    const float* __restrict__ emb,
    const float* __restrict__ Wih_f, const float* __restrict__ Whh_f,
    const float* __restrict__ bih_f, const float* __restrict__ bhh_f,
    const float* __restrict__ Wih_b, const float* __restrict__ Whh_b,
    const float* __restrict__ bih_b, const float* __restrict__ bhh_b,
    float* __restrict__ out)
{
    const int bid = blockIdx.x, tid = threadIdx.x;
    const int w = tid >> 5, lane = tid & 31;

    float* out_outputs = out;                             // [T][B][2][H]
    float* out_hidden  = out + (size_t)TT * BB * 2 * HH;  // [2][T][B][H]
    float* out_emb     = out + (size_t)4 * TT * BB * HH;  // [T][B][H]

    if (bid >= NREC) {                                    // embedding copy blocks
        int gw = (bid - NREC) * 8 + w;
        const float4* ev = (const float4*)emb;
        float4* dv = (float4*)out_emb;
        for (int n = gw; n < TT * BB; n += NEMB * 8) {
            int tok = __ldg(seq + n);
            const float4* s = ev + (size_t)tok * (HH / 4);
            float4* d = dv + (size_t)n * (HH / 4);
#pragma unroll
            for (int i = 0; i < 4; i++) d[lane + i * 32] = __ldg(s + lane + i * 32);
        }
        return;
    }

    const int dir = bid >> 6;
    const int j0 = (bid & 63) * 8;
    const int j = j0 + w;                                 // this warp's hidden unit

    const float* Wih = dir ? Wih_b : Wih_f;
    const float* Whh = dir ? Whh_b : Whh_f;
    const float* bih = dir ? bih_b : bih_f;
    const float* bhh = dir ? bhh_b : bhh_f;

    const float bi = bih[j] + bhh[j];
    const float bf = bih[HH + j] + bhh[HH + j];
    const float bg = bih[2 * HH + j] + bhh[2 * HH + j];
    const float bo = bih[3 * HH + j] + bhh[3 * HH + j];

    // persistent weights: chunks q=0..3 Wih, q=4..7 Whh; lane covers 4 consecutive k
    ull w01[32], w23[32];
#pragma unroll
    for (int q = 0; q < 8; q++) {
        const float* Ws = (q < 4) ? Wih : Whh;
        const int kb = (q & 3) * 128 + lane * 4;
        float4 vi = *(const float4*)(Ws + (size_t)j * HH + kb);
        float4 vf = *(const float4*)(Ws + (size_t)(HH + j) * HH + kb);
        float4 vg = *(const float4*)(Ws + (size_t)(2 * HH + j) * HH + kb);
        float4 vo = *(const float4*)(Ws + (size_t)(3 * HH + j) * HH + kb);
        w01[q * 4 + 0] = pk(vi.x, vf.x); w23[q * 4 + 0] = pk(vg.x, vo.x);
        w01[q * 4 + 1] = pk(vi.y, vf.y); w23[q * 4 + 1] = pk(vg.y, vo.y);
        w01[q * 4 + 2] = pk(vi.z, vf.z); w23[q * 4 + 2] = pk(vg.z, vo.z);
        w01[q * 4 + 3] = pk(vi.w, vf.w); w23[q * 4 + 3] = pk(vg.w, vo.w);
    }

    __shared__ float hb_h[8][33], hb_o[8][33];

    // zero initial h (parity 0): thread -> (b = tid>>3, jl = tid&7)
    {
        int b = tid >> 3, jl = tid & 7;
        __stcg(&g_h[dir][0][b * HH + j0 + jl], 0.f);
    }

    float c_state = 0.f, h_state = 0.f;                   // lane = batch index
    const int mylen = __ldg(lens + lane);
    unsigned int tgt = g_flags[bid];
    barrier_arrive(bid, ++tgt);                           // zeros published

    for (int t = 0; t < TT; t++) {
        const int tt = dir ? (TT - 1 - t) : t;
        const float* hcur = g_h[dir][t & 1];
        float* hnxt = g_h[dir][(t & 1) ^ 1];

        const int tok_reg = __ldg(seq + tt * BB + lane);

        // ---- phase 1: x @ Wih^T  (independent of barrier/h; hides arrive->visible latency)
        float gi = 0.f, gf = 0.f, gg = 0.f, go = 0.f;
#pragma unroll 1
        for (int b = 0; b < BB; b += 2) {
            const int tok0 = __shfl_sync(0xffffffffu, tok_reg, b);
            const int tok1 = __shfl_sync(0xffffffffu, tok_reg, b + 1);
            const float4* xs0 = (const float4*)emb + (size_t)tok0 * (HH / 4) + lane;
            const float4* xs1 = (const float4*)emb + (size_t)tok1 * (HH / 4) + lane;
            ull p0 = 0, p1 = 0, p2 = 0, p3 = 0;
            ull r0 = 0, r1 = 0, r2 = 0, r3 = 0;
#pragma unroll
            for (int q = 0; q < 4; q++) {
                mac4(w01, w23, q * 4, __ldg(xs0 + q * 32), p0, p1, p2, p3);
                mac4(w01, w23, q * 4, __ldg(xs1 + q * 32), r0, r1, r2, r3);
            }
            ull A = add2(p0, p1), Bc = add2(p2, p3);
            ull C = add2(r0, r1), D = add2(r2, r3);
#pragma unroll
            for (int s = 16; s; s >>= 1) {
                A  = add2(A,  __shfl_xor_sync(0xffffffffu, A,  s));
                Bc = add2(Bc, __shfl_xor_sync(0xffffffffu, Bc, s));
                C  = add2(C,  __shfl_xor_sync(0xffffffffu, C,  s));
                D  = add2(D,  __shfl_xor_sync(0xffffffffu, D,  s));
            }
            if (lane == b)     { up(A, gi, gf); up(Bc, gg, go); }
            if (lane == b + 1) { up(C, gi, gf); up(D,  gg, go); }
        }

        // ---- phase 2: wait for h(t), stage it, h @ Whh^T
        barrier_wait(dir, tgt);                           // usually already satisfied

        {
            const float4* s = (const float4*)hcur;        // L1-bypass: other SMs wrote it
            float4* d = (float4*)h_sm;
#pragma unroll
            for (int i = 0; i < 16; i++) d[tid + i * 256] = __ldcg(s + tid + i * 256);
        }
        __syncthreads();

#pragma unroll 1
        for (int b = 0; b < BB; b += 2) {
            const float4* hs0 = (const float4*)h_sm + b * (HH / 4) + lane;
            const float4* hs1 = hs0 + (HH / 4);
            ull p0 = 0, p1 = 0, p2 = 0, p3 = 0;
            ull r0 = 0, r1 = 0, r2 = 0, r3 = 0;
#pragma unroll
            for (int q = 0; q < 4; q++) {
                mac4(w01, w23, (q + 4) * 4, hs0[q * 32], p0, p1, p2, p3);
                mac4(w01, w23, (q + 4) * 4, hs1[q * 32], r0, r1, r2, r3);
            }
            ull A = add2(p0, p1), Bc = add2(p2, p3);
            ull C = add2(r0, r1), D = add2(r2, r3);
#pragma unroll
            for (int s = 16; s; s >>= 1) {
                A  = add2(A,  __shfl_xor_sync(0xffffffffu, A,  s));
                Bc = add2(Bc, __shfl_xor_sync(0xffffffffu, Bc, s));
                C  = add2(C,  __shfl_xor_sync(0xffffffffu, C,  s));
                D  = add2(D,  __shfl_xor_sync(0xffffffffu, D,  s));
            }
            float u, v;
            if (lane == b)     { up(A, u, v); gi += u; gf += v; up(Bc, u, v); gg += u; go += v; }
            if (lane == b + 1) { up(C, u, v); gi += u; gf += v; up(D,  u, v); gg += u; go += v; }
        }

        // ---- gates + state (lane = batch)
        float iv = sigm(gi + bi), fv = sigm(gf + bf);
        float gv = tanh_(gg + bg), ov = sigm(go + bo);
        float cn = fv * c_state + iv * gv;
        float hn = ov * tanh_(cn);
        const bool m = (tt < mylen);
        h_state = m ? hn : h_state;
        c_state = m ? cn : c_state;
        float oz = m ? hn : 0.f;

        hb_h[w][lane] = h_state;
        hb_o[w][lane] = oz;
        __syncthreads();

        // transposed epilogue: thread -> (b, jl); 8 consecutive j = 32B per store
        {
            int b = tid >> 3, jl = tid & 7, jj = j0 + jl;
            float hs_ = hb_h[jl][b], os_ = hb_o[jl][b];
            __stcg(&hnxt[b * HH + jj], hs_);
            out_outputs[((size_t)(tt * BB + b) * 2 + dir) * HH + jj] = os_;
            out_hidden[((size_t)(dir * TT + tt) * BB + b) * HH + jj] = os_;
        }

        barrier_arrive(bid, ++tgt);       // publish h(t+1); next iter's x-part hides the wait
    }
}

extern "C" void kernel_launch(void* const* d_in, const int* in_sizes, int n_in,
                              void* d_out, int out_size) {
    (void)in_sizes; (void)n_in; (void)out_size;
    static int smem_set = 0;
    if (!smem_set) {
        cudaFuncSetAttribute(bilstm_kernel, cudaFuncAttributeMaxDynamicSharedMemorySize,
                             BB * HH * (int)sizeof(float));
        smem_set = 1;
    }
    bilstm_kernel<<<NREC + NEMB, 256, BB * HH * sizeof(float)>>>(
        (const int*)d_in[0], (const int*)d_in[1], (const float*)d_in[2],
        (const float*)d_in[3], (const float*)d_in[4], (const float*)d_in[5], (const float*)d_in[6],
        (const float*)d_in[7], (const float*)d_in[8], (const float*)d_in[9], (const float*)d_in[10],
        (float*)d_out);
}

// round 8
// speedup vs baseline: 1.7147x; 1.7147x over previous
#include <cuda_runtime.h>

#define TT 512
#define BB 32
#define HH 512
#define NREC 128
#define XW_COLS 16384            // T*B
#define XW_ROWS 4096             // 2 dirs * 4 gates * H

__device__ float g_h[2][2][BB * HH];        // [dir][parity][b*H+j]
__device__ unsigned int g_flags[NREC];      // monotonic barrier flags
__device__ unsigned int g_dead;             // timeout poison
__device__ float g_xw[(size_t)XW_ROWS * XW_COLS];   // 256MB scratch: XW[r][n]

typedef unsigned long long ull;

static __device__ __forceinline__ ull pk(float x, float y) {
    ull r; asm("mov.b64 %0,{%1,%2};" : "=l"(r) : "f"(x), "f"(y)); return r;
}
static __device__ __forceinline__ void up(ull v, float& x, float& y) {
    asm("mov.b64 {%0,%1},%2;" : "=f"(x), "=f"(y) : "l"(v));
}
static __device__ __forceinline__ ull fma2(ull a, ull b, ull c) {
    ull d; asm("fma.rn.f32x2 %0,%1,%2,%3;" : "=l"(d) : "l"(a), "l"(b), "l"(c)); return d;
}
static __device__ __forceinline__ ull add2(ull a, ull b) {
    ull d; asm("add.rn.f32x2 %0,%1,%2;" : "=l"(d) : "l"(a), "l"(b)); return d;
}
static __device__ __forceinline__ float sigm(float x) {
    return __fdividef(1.f, 1.f + __expf(-x));
}
static __device__ __forceinline__ float tanh_(float x) {
    float a = fabsf(x), e = __expf(-2.f * a);
    return copysignf(__fdividef(1.f - e, 1.f + e), x);
}

// ---------------- embedding gather: out_emb[T][B][H] = emb[seq] ----------------
__global__ void embed_kernel(const int* __restrict__ seq,
                             const float* __restrict__ emb,
                             float* __restrict__ out_emb)
{
    int gw = blockIdx.x * 8 + (threadIdx.x >> 5);
    int lane = threadIdx.x & 31;
    const float4* ev = (const float4*)emb;
    float4* dv = (float4*)out_emb;
    for (int n = gw; n < TT * BB; n += gridDim.x * 8) {
        int tok = __ldg(seq + n);
        const float4* s = ev + (size_t)tok * (HH / 4);
        float4* d = dv + (size_t)n * (HH / 4);
#pragma unroll
        for (int i = 0; i < 4; i++) d[lane + i * 32] = __ldg(s + lane + i * 32);
    }
}

// ---------------- XW GEMM: g_xw[r][n] = sum_k W[r][k] * X[n][k] ----------------
// r = dir*2048 + gate*512 + j; n = t*B + b; X = out_emb.
// 128(M) x 64(N) tile per block, K chunks of 16, register-prefetched.
__global__ void __launch_bounds__(256, 1) xw_gemm_kernel(
    const float* __restrict__ Wih_f, const float* __restrict__ Wih_b,
    const float* __restrict__ X)
{
    __shared__ float As[16][132];     // [k][m], padded
    __shared__ float Bs[16][68];      // [k][n]
    const int tid = threadIdx.x;
    const int mt = blockIdx.x & 31, nt = blockIdx.x >> 5;
    const int m0 = mt * 128, n0 = nt * 64;
    const float* A = (m0 < 2048) ? (Wih_f + (size_t)m0 * HH)
                                 : (Wih_b + (size_t)(m0 - 2048) * HH);
    const int ar = tid >> 1, af = (tid & 1) * 2;    // A: row 0..127, float4 pair
    const int br = tid >> 2, bf = tid & 3;          // B: row 0..63,  float4 idx
    const int tm = tid >> 4, tn = tid & 15;         // micro: 8 m x 4 n

    float4 ra0, ra1, rb;
    {
        const float4* Ap = (const float4*)(A + (size_t)ar * HH);
        ra0 = Ap[af]; ra1 = Ap[af + 1];
        rb = ((const float4*)(X + (size_t)(n0 + br) * HH))[bf];
    }
    ull acc[4][4];
#pragma unroll
    for (int i = 0; i < 4; i++)
#pragma unroll
        for (int n = 0; n < 4; n++) acc[i][n] = 0;

    for (int c = 0; c < 32; c++) {
        {
            const int kb = af * 4;
            As[kb + 0][ar] = ra0.x; As[kb + 1][ar] = ra0.y;
            As[kb + 2][ar] = ra0.z; As[kb + 3][ar] = ra0.w;
            As[kb + 4][ar] = ra1.x; As[kb + 5][ar] = ra1.y;
            As[kb + 6][ar] = ra1.z; As[kb + 7][ar] = ra1.w;
            const int kc = bf * 4;
            Bs[kc + 0][br] = rb.x; Bs[kc + 1][br] = rb.y;
            Bs[kc + 2][br] = rb.z; Bs[kc + 3][br] = rb.w;
        }
        __syncthreads();
        if (c < 31) {                                  // prefetch next K chunk
            const int k0 = (c + 1) * 16;
            const float4* Ap = (const float4*)(A + (size_t)ar * HH + k0);
            ra0 = Ap[af]; ra1 = Ap[af + 1];
            rb = ((const float4*)(X + (size_t)(n0 + br) * HH + k0))[bf];
        }
#pragma unroll
        for (int k = 0; k < 16; k++) {
            float4 va = *(const float4*)&As[k][tm * 8];
            float4 vb = *(const float4*)&As[k][tm * 8 + 4];
            float4 vn = *(const float4*)&Bs[k][tn * 4];
            ull ap0 = pk(va.x, va.y), ap1 = pk(va.z, va.w);
            ull ap2 = pk(vb.x, vb.y), ap3 = pk(vb.z, vb.w);
            ull b0 = pk(vn.x, vn.x), b1 = pk(vn.y, vn.y);
            ull b2 = pk(vn.z, vn.z), b3 = pk(vn.w, vn.w);
            acc[0][0] = fma2(ap0, b0, acc[0][0]); acc[0][1] = fma2(ap0, b1, acc[0][1]);
            acc[0][2] = fma2(ap0, b2, acc[0][2]); acc[0][3] = fma2(ap0, b3, acc[0][3]);
            acc[1][0] = fma2(ap1, b0, acc[1][0]); acc[1][1] = fma2(ap1, b1, acc[1][1]);
            acc[1][2] = fma2(ap1, b2, acc[1][2]); acc[1][3] = fma2(ap1, b3, acc[1][3]);
            acc[2][0] = fma2(ap2, b0, acc[2][0]); acc[2][1] = fma2(ap2, b1, acc[2][1]);
            acc[2][2] = fma2(ap2, b2, acc[2][2]); acc[2][3] = fma2(ap2, b3, acc[2][3]);
            acc[3][0] = fma2(ap3, b0, acc[3][0]); acc[3][1] = fma2(ap3, b1, acc[3][1]);
            acc[3][2] = fma2(ap3, b2, acc[3][2]); acc[3][3] = fma2(ap3, b3, acc[3][3]);
        }
        __syncthreads();
    }
#pragma unroll
    for (int i = 0; i < 4; i++) {
        const int m = m0 + tm * 8 + i * 2;
#pragma unroll
        for (int n = 0; n < 4; n++) {
            float lo, hi; up(acc[i][n], lo, hi);
            size_t base = (size_t)m * XW_COLS + n0 + tn * 4 + n;
            g_xw[base] = lo;
            g_xw[base + XW_COLS] = hi;
        }
    }
}

// 8 packed FMAs into one (if, go) accumulator pair
static __device__ __forceinline__ void mac4_2(const ull* W01, const ull* W23, int q4, float4 v,
                                              ull& aif, ull& ago) {
    ull d0 = pk(v.x, v.x), d1 = pk(v.y, v.y), d2 = pk(v.z, v.z), d3 = pk(v.w, v.w);
    aif = fma2(W01[q4 + 0], d0, aif); ago = fma2(W23[q4 + 0], d0, ago);
    aif = fma2(W01[q4 + 1], d1, aif); ago = fma2(W23[q4 + 1], d1, ago);
    aif = fma2(W01[q4 + 2], d2, aif); ago = fma2(W23[q4 + 2], d2, ago);
    aif = fma2(W01[q4 + 3], d3, aif); ago = fma2(W23[q4 + 3], d3, ago);
}

// fused barrier among 64 blocks of a direction; monotonic, wrap-safe, timeout-poisoned
static __device__ __forceinline__ void gbar(int dir, int bid, unsigned int tgt) {
    __threadfence();
    __syncthreads();
    if (threadIdx.x < 32) {
        if (threadIdx.x == 0) atomicExch(&g_flags[bid], tgt);
        volatile unsigned int* f = g_flags + dir * 64;
        volatile unsigned int* dead = &g_dead;
        unsigned int it = 0;
        bool ok;
        do {
            unsigned int a = f[threadIdx.x], b = f[threadIdx.x + 32];
            ok = ((int)(a - tgt) >= 0) && ((int)(b - tgt) >= 0);
            if (++it > (1u << 18)) {
                if (threadIdx.x == 0) atomicExch(&g_dead, 1u);
                break;
            }
        } while (!__all_sync(0xffffffffu, ok) && *dead == 0u);
        __threadfence();
    }
    __syncthreads();
}

extern __shared__ float h_sm[];               // BB*HH floats = 64KB

// ---------------- serial recurrence: h-part only ----------------
__global__ void __launch_bounds__(256, 1) bilstm_loop_kernel(
    const int* __restrict__ lens,
    const float* __restrict__ Whh_f, const float* __restrict__ bih_f, const float* __restrict__ bhh_f,
    const float* __restrict__ Whh_b, const float* __restrict__ bih_b, const float* __restrict__ bhh_b,
    float* __restrict__ out)
{
    const int bid = blockIdx.x, tid = threadIdx.x;
    const int w = tid >> 5, lane = tid & 31;
    const int dir = bid >> 6;
    const int j0 = (bid & 63) * 8;
    const int j = j0 + w;

    float* out_outputs = out;                             // [T][B][2][H]
    float* out_hidden  = out + (size_t)TT * BB * 2 * HH;  // [2][T][B][H]

    const float* Whh = dir ? Whh_b : Whh_f;
    const float* bih = dir ? bih_b : bih_f;
    const float* bhh = dir ? bhh_b : bhh_f;

    const float bi = bih[j] + bhh[j];
    const float bf = bih[HH + j] + bhh[HH + j];
    const float bg = bih[2 * HH + j] + bhh[2 * HH + j];
    const float bo = bih[3 * HH + j] + bhh[3 * HH + j];

    // persistent Whh slice: 4 chunks of 128 k, 4 consecutive k per lane per chunk
    ull w01[16], w23[16];
#pragma unroll
    for (int q = 0; q < 4; q++) {
        const int kb = q * 128 + lane * 4;
        float4 vi = *(const float4*)(Whh + (size_t)j * HH + kb);
        float4 vf = *(const float4*)(Whh + (size_t)(HH + j) * HH + kb);
        float4 vg = *(const float4*)(Whh + (size_t)(2 * HH + j) * HH + kb);
        float4 vo = *(const float4*)(Whh + (size_t)(3 * HH + j) * HH + kb);
        w01[q * 4 + 0] = pk(vi.x, vf.x); w23[q * 4 + 0] = pk(vg.x, vo.x);
        w01[q * 4 + 1] = pk(vi.y, vf.y); w23[q * 4 + 1] = pk(vg.y, vo.y);
        w01[q * 4 + 2] = pk(vi.z, vf.z); w23[q * 4 + 2] = pk(vg.z, vo.z);
        w01[q * 4 + 3] = pk(vi.w, vf.w); w23[q * 4 + 3] = pk(vg.w, vo.w);
    }

    __shared__ float hb_h[8][33], hb_o[8][33];

    {   // zero initial h (parity 0)
        int b = tid >> 3, jl = tid & 7;
        __stcg(&g_h[dir][0][b * HH + j0 + jl], 0.f);
    }

    float c_state = 0.f, h_state = 0.f;                   // lane = batch
    const int mylen = __ldg(lens + lane);
    unsigned int tgt = g_flags[bid];
    gbar(dir, bid, ++tgt);

    const float* xwj = g_xw + (size_t)(dir * 2048 + j) * XW_COLS + lane;

    for (int t = 0; t < TT; t++) {
        const int tt = dir ? (TT - 1 - t) : t;
        const float* hcur = g_h[dir][t & 1];
        float* hnxt = g_h[dir][(t & 1) ^ 1];

        // precomputed x-gates for (unit j, step tt): 4 coalesced loads, latency hidden below
        const float* xp = xwj + tt * 32;
        float xg0 = __ldg(xp);
        float xg1 = __ldg(xp + (size_t)512 * XW_COLS);
        float xg2 = __ldg(xp + (size_t)1024 * XW_COLS);
        float xg3 = __ldg(xp + (size_t)1536 * XW_COLS);

        // stage h to SMEM, L1-bypassed (other SMs wrote it; L1 persists in-kernel)
        {
            const float4* s = (const float4*)hcur;
            float4* d = (float4*)h_sm;
#pragma unroll
            for (int i = 0; i < 16; i++) d[tid + i * 256] = __ldcg(s + tid + i * 256);
        }
        __syncthreads();

        float gi = 0.f, gf = 0.f, gg = 0.f, go = 0.f;
#pragma unroll 1
        for (int b = 0; b < BB; b += 4) {                 // 8 reduction chains in flight
            const float4* hs0 = (const float4*)h_sm + (b + 0) * (HH / 4) + lane;
            const float4* hs1 = hs0 + (HH / 4);
            const float4* hs2 = hs1 + (HH / 4);
            const float4* hs3 = hs2 + (HH / 4);
            ull aif0 = 0, ago0 = 0, aif1 = 0, ago1 = 0;
            ull aif2 = 0, ago2 = 0, aif3 = 0, ago3 = 0;
#pragma unroll
            for (int q = 0; q < 4; q++) {
                mac4_2(w01, w23, q * 4, hs0[q * 32], aif0, ago0);
                mac4_2(w01, w23, q * 4, hs1[q * 32], aif1, ago1);
                mac4_2(w01, w23, q * 4, hs2[q * 32], aif2, ago2);
                mac4_2(w01, w23, q * 4, hs3[q * 32], aif3, ago3);
            }
#pragma unroll
            for (int s = 16; s; s >>= 1) {
                aif0 = add2(aif0, __shfl_xor_sync(0xffffffffu, aif0, s));
                ago0 = add2(ago0, __shfl_xor_sync(0xffffffffu, ago0, s));
                aif1 = add2(aif1, __shfl_xor_sync(0xffffffffu, aif1, s));
                ago1 = add2(ago1, __shfl_xor_sync(0xffffffffu, ago1, s));
                aif2 = add2(aif2, __shfl_xor_sync(0xffffffffu, aif2, s));
                ago2 = add2(ago2, __shfl_xor_sync(0xffffffffu, ago2, s));
                aif3 = add2(aif3, __shfl_xor_sync(0xffffffffu, aif3, s));
                ago3 = add2(ago3, __shfl_xor_sync(0xffffffffu, ago3, s));
            }
            if (lane == b)     { up(aif0, gi, gf); up(ago0, gg, go); }
            if (lane == b + 1) { up(aif1, gi, gf); up(ago1, gg, go); }
            if (lane == b + 2) { up(aif2, gi, gf); up(ago2, gg, go); }
            if (lane == b + 3) { up(aif3, gi, gf); up(ago3, gg, go); }
        }

        // gates (lane = batch)
        float iv = sigm(gi + xg0 + bi), fv = sigm(gf + xg1 + bf);
        float gv = tanh_(gg + xg2 + bg), ov = sigm(go + xg3 + bo);
        float cn = fv * c_state + iv * gv;
        float hn = ov * tanh_(cn);
        const bool m = (tt < mylen);
        h_state = m ? hn : h_state;
        c_state = m ? cn : c_state;
        float oz = m ? hn : 0.f;

        hb_h[w][lane] = h_state;
        hb_o[w][lane] = oz;
        __syncthreads();

        {   // transposed epilogue: thread -> (b, jl); 32B coalesced stores
            int b = tid >> 3, jl = tid & 7, jj = j0 + jl;
            float hs_ = hb_h[jl][b], os_ = hb_o[jl][b];
            __stcg(&hnxt[b * HH + jj], hs_);
            out_outputs[((size_t)(tt * BB + b) * 2 + dir) * HH + jj] = os_;
            out_hidden[((size_t)(dir * TT + tt) * BB + b) * HH + jj] = os_;
        }

        gbar(dir, bid, ++tgt);
    }
}

extern "C" void kernel_launch(void* const* d_in, const int* in_sizes, int n_in,
                              void* d_out, int out_size) {
    (void)in_sizes; (void)n_in; (void)out_size;
    const int*   seq   = (const int*)d_in[0];
    const int*   lens  = (const int*)d_in[1];
    const float* emb   = (const float*)d_in[2];
    const float* Wih_f = (const float*)d_in[3];
    const float* Whh_f = (const float*)d_in[4];
    const float* bih_f = (const float*)d_in[5];
    const float* bhh_f = (const float*)d_in[6];
    const float* Wih_b = (const float*)d_in[7];
    const float* Whh_b = (const float*)d_in[8];
    const float* bih_b = (const float*)d_in[9];
    const float* bhh_b = (const float*)d_in[10];
    float* out = (float*)d_out;
    float* out_emb = out + (size_t)4 * TT * BB * HH;

    cudaFuncSetAttribute(bilstm_loop_kernel, cudaFuncAttributeMaxDynamicSharedMemorySize,
                         BB * HH * (int)sizeof(float));

    embed_kernel<<<148, 256>>>(seq, emb, out_emb);
    xw_gemm_kernel<<<(XW_ROWS / 128) * (XW_COLS / 64), 256>>>(Wih_f, Wih_b, out_emb);
    bilstm_loop_kernel<<<NREC, 256, BB * HH * sizeof(float)>>>(
        lens, Whh_f, bih_f, bhh_f, Whh_b, bih_b, bhh_b, out);
}